// round 16
// baseline (speedup 1.0000x reference)
#include <cuda_runtime.h>
#include <cuda_bf16.h>
#include <math.h>
#include <stdint.h>

#define Bdim 256
#define Tdim 300
#define XDdim 513
#define XDpad 544
#define Hdim 128
#define G4 512
#define ZDdim 16
#define TPAD 384
#define NROWS (Bdim * Tdim)

__device__ float d_P[Tdim * Bdim * G4];
__device__ float d_G[Tdim * Bdim * Hdim];
__device__ float d_Z[Tdim * Bdim * ZDdim];
__device__ __nv_bfloat16 d_xh[(size_t)Bdim * Tdim * XDpad];
__device__ __nv_bfloat16 d_xl[(size_t)Bdim * Tdim * XDpad];
__device__ __nv_bfloat16 d_Wh[G4 * XDpad];
__device__ __nv_bfloat16 d_Wl[G4 * XDpad];
__device__ __nv_bfloat16 d_h1h[(size_t)Bdim * TPAD * Hdim];
__device__ __nv_bfloat16 d_h1l[(size_t)Bdim * TPAD * Hdim];
__device__ __nv_bfloat16 d_h2h[(size_t)Bdim * TPAD * Hdim];
__device__ __nv_bfloat16 d_h2l[(size_t)Bdim * TPAD * Hdim];
__device__ __nv_bfloat16 d_gyh[640 * Hdim];
__device__ __nv_bfloat16 d_gyl[640 * Hdim];
__device__ __nv_bfloat16 d_zx2h[Hdim * Hdim];
__device__ __nv_bfloat16 d_zx2l[Hdim * Hdim];

__device__ __forceinline__ float sigm(float x) { return 1.f / (1.f + expf(-x)); }
__device__ __forceinline__ float tanh_hw(float x) {
    float r;
    asm("tanh.approx.f32 %0, %1;" : "=f"(r) : "f"(x));
    return r;
}
__device__ __forceinline__ float sig_hw(float x) {
    return fmaf(0.5f, tanh_hw(0.5f * x), 0.5f);
}
__device__ __forceinline__ float tanhfast(float x) {
    return 1.f - __fdividef(2.f, __expf(2.f * x) + 1.f);
}

__device__ __forceinline__ uint32_t smem_u32(const void* p) {
    uint32_t a;
    asm("{ .reg .u64 tmp; cvta.to.shared.u64 tmp, %1; cvt.u32.u64 %0, tmp; }"
        : "=r"(a) : "l"(p));
    return a;
}
__device__ __forceinline__ void cpa16(uint32_t dst, const void* src, int valid) {
    asm volatile("cp.async.ca.shared.global [%0], [%1], 16, %2;"
                 :: "r"(dst), "l"(__cvta_generic_to_global(src)), "r"(valid) : "memory");
}
#define CP_COMMIT() asm volatile("cp.async.commit_group;" ::: "memory")
#define CP_WAIT1()  asm volatile("cp.async.wait_group 1;" ::: "memory")
#define CP_WAIT0()  asm volatile("cp.async.wait_group 0;" ::: "memory")
#define LDSM4(r, addr)                                                           \
    asm volatile("ldmatrix.sync.aligned.m8n8.x4.shared.b16 {%0,%1,%2,%3}, [%4];" \
                 : "=r"((r)[0]), "=r"((r)[1]), "=r"((r)[2]), "=r"((r)[3]) : "r"(addr))
#define MMA16816(d, a, b0v, b1v)                                                 \
    asm volatile("mma.sync.aligned.m16n8k16.row.col.f32.bf16.bf16.f32 "          \
                 "{%0,%1,%2,%3}, {%4,%5,%6,%7}, {%8,%9}, {%0,%1,%2,%3};"         \
                 : "+f"((d)[0]), "+f"((d)[1]), "+f"((d)[2]), "+f"((d)[3])        \
                 : "r"((a)[0]), "r"((a)[1]), "r"((a)[2]), "r"((a)[3]),           \
                   "r"(b0v), "r"(b1v))

// ============== K0a: x transpose+split ==============
__global__ __launch_bounds__(256) void convert_x_kernel(const float* __restrict__ x) {
    __shared__ float tileS[32][33];
    const int dt = blockIdx.x % 17, tt = blockIdx.x / 17;
    const int b = blockIdx.y;
    const int d0 = dt * 32, t0 = tt * 32;
    const int r0 = threadIdx.x >> 5, c = threadIdx.x & 31;
#pragma unroll
    for (int i = 0; i < 4; ++i) {
        int d = d0 + r0 + i * 8, t = t0 + c;
        float v = 0.f;
        if (d < XDdim && t < Tdim) v = x[((size_t)b * XDdim + d) * Tdim + t];
        tileS[r0 + i * 8][c] = v;
    }
    __syncthreads();
#pragma unroll
    for (int i = 0; i < 4; ++i) {
        int trow = t0 + r0 + i * 8, d = d0 + c;
        if (trow < Tdim) {
            float v = tileS[c][r0 + i * 8];
            __nv_bfloat16 h = __float2bfloat16(v);
            __nv_bfloat16 l = __float2bfloat16(v - __bfloat162float(h));
            size_t o = ((size_t)b * Tdim + trow) * XDpad + d;
            d_xh[o] = h; d_xl[o] = l;
        }
    }
}

// ============== K0b: Wih split ==============
__global__ __launch_bounds__(256) void convert_w_kernel(const float* __restrict__ W) {
    int idx = blockIdx.x * 256 + threadIdx.x;
    if (idx >= G4 * XDpad) return;
    int d = idx % XDpad, j = idx / XDpad;
    float v = (d < XDdim) ? W[(size_t)j * XDdim + d] : 0.f;
    __nv_bfloat16 h = __float2bfloat16(v);
    __nv_bfloat16 l = __float2bfloat16(v - __bfloat162float(h));
    d_Wh[idx] = h; d_Wl[idx] = l;
}

// ============== K0c: Wgy split ==============
__global__ __launch_bounds__(256) void convert_gy_kernel(const float* __restrict__ W) {
    int idx = blockIdx.x * 256 + threadIdx.x;
    if (idx >= 640 * Hdim) return;
    int d = idx >> 7;
    float v = (d < XDdim) ? W[idx] : 0.f;
    __nv_bfloat16 h = __float2bfloat16(v);
    __nv_bfloat16 l = __float2bfloat16(v - __bfloat162float(h));
    d_gyh[idx] = h; d_gyl[idx] = l;
}

// ============== K0d: Wzx2 split (128x128) ==============
__global__ __launch_bounds__(256) void convert_zx2_kernel(const float* __restrict__ W) {
    int idx = blockIdx.x * 256 + threadIdx.x;
    if (idx >= Hdim * Hdim) return;
    float v = W[idx];
    __nv_bfloat16 h = __float2bfloat16(v);
    __nv_bfloat16 l = __float2bfloat16(v - __bfloat162float(h));
    d_zx2h[idx] = h; d_zx2l[idx] = l;
}

// ============== K1: fused-term HMMA GEMM (unchanged) ==============
#define ROWB 80
#define STG2 40960
#define MMA_SMEM2 (81920 + 512)
#define NCHUNK2 17

__global__ __launch_bounds__(256, 2) void gemm_mma_kernel(
    const float* __restrict__ bih, const float* __restrict__ bhh) {
    extern __shared__ char sm[];
    const uint32_t smb = smem_u32(sm);
    const int tid = threadIdx.x, lane = tid & 31, w = tid >> 5;
    const int j0 = blockIdx.x * 128;
    const int rt0 = blockIdx.y * 128;

    float* biasS = (float*)(sm + 81920);
    if (tid < 128) biasS[tid] = bih[j0 + tid] + bhh[j0 + tid];

    auto load_stage = [&](int st, int dk) {
        uint32_t base = smb + st * STG2;
#pragma unroll
        for (int i = 0; i < 8; ++i) {
            const __nv_bfloat16* M = (i < 2) ? d_Wh : (i < 4) ? d_Wl : (i < 6) ? d_xh : d_xl;
            int rem = (i & 1) * 256 + tid;
            int row = rem >> 2, seg = rem & 3;
            size_t go = (i < 4)
                ? ((size_t)(j0 + row) * XDpad + dk * 32 + seg * 8)
                : ((size_t)(rt0 + row) * XDpad + dk * 32 + seg * 8);
            cpa16(base + (i >> 1) * 10240 + row * ROWB + seg * 16, M + go, 16);
        }
        CP_COMMIT();
    };

    float acc[4][4][4];
#pragma unroll
    for (int mi = 0; mi < 4; ++mi)
#pragma unroll
        for (int ni = 0; ni < 4; ++ni)
#pragma unroll
            for (int q = 0; q < 4; ++q) acc[mi][ni][q] = 0.f;

    const int m0 = (w >> 2) * 64, n0 = (w & 3) * 32;
    const uint32_t partA = ((lane & 7) + ((lane >> 3) & 1) * 8) * ROWB + ((lane >> 4) & 1) * 16;
    const uint32_t partB = (((lane >> 4) & 1) * 8 + (lane & 7)) * ROWB + ((lane >> 3) & 1) * 16;

    load_stage(0, 0);
    int st = 0;

    for (int c = 0; c < NCHUNK2; ++c) {
        if (c < NCHUNK2 - 1) { load_stage(st ^ 1, c + 1); CP_WAIT1(); }
        else                 { CP_WAIT0(); }
        __syncthreads();

        uint32_t sah = smb + st * STG2 + m0 * ROWB;
        uint32_t sal = sah + 10240;
        uint32_t sbh = smb + st * STG2 + 20480 + n0 * ROWB;
        uint32_t sbl = sbh + 10240;
#pragma unroll
        for (int k16 = 0; k16 < 2; ++k16) {
            uint32_t bh[2][4], bl[2][4], af[4][4];
#pragma unroll
            for (int np = 0; np < 2; ++np) {
                LDSM4(bh[np], sbh + np * 16 * ROWB + k16 * 32 + partB);
                LDSM4(bl[np], sbl + np * 16 * ROWB + k16 * 32 + partB);
            }
#pragma unroll
            for (int mi = 0; mi < 4; ++mi)
                LDSM4(af[mi], sah + mi * 16 * ROWB + k16 * 32 + partA);
#pragma unroll
            for (int mi = 0; mi < 4; ++mi)
#pragma unroll
                for (int ni = 0; ni < 4; ++ni) {
                    MMA16816(acc[mi][ni], af[mi], bh[ni >> 1][(ni & 1) * 2],
                             bh[ni >> 1][(ni & 1) * 2 + 1]);
                    MMA16816(acc[mi][ni], af[mi], bl[ni >> 1][(ni & 1) * 2],
                             bl[ni >> 1][(ni & 1) * 2 + 1]);
                }
#pragma unroll
            for (int mi = 0; mi < 4; ++mi)
                LDSM4(af[mi], sal + mi * 16 * ROWB + k16 * 32 + partA);
#pragma unroll
            for (int mi = 0; mi < 4; ++mi)
#pragma unroll
                for (int ni = 0; ni < 4; ++ni)
                    MMA16816(acc[mi][ni], af[mi], bh[ni >> 1][(ni & 1) * 2],
                             bh[ni >> 1][(ni & 1) * 2 + 1]);
        }
        __syncthreads();
        st ^= 1;
    }

    float* outS = (float*)sm;
    const int gid = lane >> 2, tq = lane & 3;
#pragma unroll
    for (int mi = 0; mi < 4; ++mi)
#pragma unroll
        for (int ni = 0; ni < 4; ++ni) {
            int jrow = m0 + 16 * mi + gid;
            int tcol = n0 + 8 * ni + tq * 2;
            outS[tcol * 132 + jrow]           = acc[mi][ni][0];
            outS[(tcol + 1) * 132 + jrow]     = acc[mi][ni][1];
            outS[tcol * 132 + jrow + 8]       = acc[mi][ni][2];
            outS[(tcol + 1) * 132 + jrow + 8] = acc[mi][ni][3];
        }
    __syncthreads();

    for (int i = tid; i < 128 * 32; i += 256) {
        int r = i >> 5, q = i & 31;
        int rr = rt0 + r;
        int b = rr / Tdim, t = rr - b * Tdim;
        float4 v = *(float4*)&outS[r * 132 + q * 4];
        float4 bb = *(float4*)&biasS[q * 4];
        v.x += bb.x; v.y += bb.y; v.z += bb.z; v.w += bb.w;
        *(float4*)&d_P[((size_t)t * Bdim + b) * G4 + j0 + q * 4] = v;
    }
}

// ============== K1y: y = exp(Wgy @ h2 + bgy) (unchanged) ==============
#define NCHUNK_Y2 4
__global__ __launch_bounds__(256, 2) void ygemm_kernel(
    const float* __restrict__ bgy, float* __restrict__ y_out) {
    extern __shared__ char sm[];
    const uint32_t smb = smem_u32(sm);
    const int tid = threadIdx.x, lane = tid & 31, w = tid >> 5;
    const int d0 = blockIdx.x * 128;
    const int rt0 = blockIdx.y * 128;

    float* biasS = (float*)(sm + 81920);
    if (tid < 128) biasS[tid] = (d0 + tid < XDdim) ? bgy[d0 + tid] : 0.f;

    const int rowE = tid >> 2, rowO = 64 + (tid >> 2);
    const int rrE = rt0 + rowE, rrO = rt0 + rowO;
    const int bE = rrE / Tdim, tE = rrE - bE * Tdim;
    const int bO = rrO / Tdim, tO = rrO - bO * Tdim;
    const size_t boffE = ((size_t)bE * TPAD + tE) * Hdim;
    const size_t boffO = ((size_t)bO * TPAD + tO) * Hdim;

    auto load_stage = [&](int st, int dk) {
        uint32_t base = smb + st * STG2;
#pragma unroll
        for (int i = 0; i < 8; ++i) {
            int rem = (i & 1) * 256 + tid;
            int row = rem >> 2, seg = rem & 3;
            const __nv_bfloat16* src;
            if (i < 4) {
                const __nv_bfloat16* M = (i < 2) ? d_gyh : d_gyl;
                src = M + (size_t)(d0 + row) * Hdim + dk * 32 + seg * 8;
            } else {
                const __nv_bfloat16* M = (i < 6) ? d_h2h : d_h2l;
                src = M + ((i & 1) ? boffO : boffE) + dk * 32 + seg * 8;
            }
            cpa16(base + (i >> 1) * 10240 + row * ROWB + seg * 16, src, 16);
        }
        CP_COMMIT();
    };

    float acc[4][4][4];
#pragma unroll
    for (int mi = 0; mi < 4; ++mi)
#pragma unroll
        for (int ni = 0; ni < 4; ++ni)
#pragma unroll
            for (int q = 0; q < 4; ++q) acc[mi][ni][q] = 0.f;

    const int m0 = (w >> 2) * 64, n0 = (w & 3) * 32;
    const uint32_t partA = ((lane & 7) + ((lane >> 3) & 1) * 8) * ROWB + ((lane >> 4) & 1) * 16;
    const uint32_t partB = (((lane >> 4) & 1) * 8 + (lane & 7)) * ROWB + ((lane >> 3) & 1) * 16;

    load_stage(0, 0);
    int st = 0;

    for (int c = 0; c < NCHUNK_Y2; ++c) {
        if (c < NCHUNK_Y2 - 1) { load_stage(st ^ 1, c + 1); CP_WAIT1(); }
        else                   { CP_WAIT0(); }
        __syncthreads();

        uint32_t sah = smb + st * STG2 + m0 * ROWB;
        uint32_t sal = sah + 10240;
        uint32_t sbh = smb + st * STG2 + 20480 + n0 * ROWB;
        uint32_t sbl = sbh + 10240;
#pragma unroll
        for (int k16 = 0; k16 < 2; ++k16) {
            uint32_t bh[2][4], bl[2][4], af[4][4];
#pragma unroll
            for (int np = 0; np < 2; ++np) {
                LDSM4(bh[np], sbh + np * 16 * ROWB + k16 * 32 + partB);
                LDSM4(bl[np], sbl + np * 16 * ROWB + k16 * 32 + partB);
            }
#pragma unroll
            for (int mi = 0; mi < 4; ++mi)
                LDSM4(af[mi], sah + mi * 16 * ROWB + k16 * 32 + partA);
#pragma unroll
            for (int mi = 0; mi < 4; ++mi)
#pragma unroll
                for (int ni = 0; ni < 4; ++ni) {
                    MMA16816(acc[mi][ni], af[mi], bh[ni >> 1][(ni & 1) * 2],
                             bh[ni >> 1][(ni & 1) * 2 + 1]);
                    MMA16816(acc[mi][ni], af[mi], bl[ni >> 1][(ni & 1) * 2],
                             bl[ni >> 1][(ni & 1) * 2 + 1]);
                }
#pragma unroll
            for (int mi = 0; mi < 4; ++mi)
                LDSM4(af[mi], sal + mi * 16 * ROWB + k16 * 32 + partA);
#pragma unroll
            for (int mi = 0; mi < 4; ++mi)
#pragma unroll
                for (int ni = 0; ni < 4; ++ni)
                    MMA16816(acc[mi][ni], af[mi], bh[ni >> 1][(ni & 1) * 2],
                             bh[ni >> 1][(ni & 1) * 2 + 1]);
        }
        __syncthreads();
        st ^= 1;
    }

    float* outS = (float*)sm;
    const int gid = lane >> 2, tq = lane & 3;
#pragma unroll
    for (int mi = 0; mi < 4; ++mi)
#pragma unroll
        for (int ni = 0; ni < 4; ++ni) {
            int jrow = m0 + 16 * mi + gid;
            int tcol = n0 + 8 * ni + tq * 2;
            float b0 = biasS[jrow], b8 = biasS[jrow + 8];
            outS[jrow * 132 + tcol]           = expf(acc[mi][ni][0] + b0);
            outS[jrow * 132 + tcol + 1]       = expf(acc[mi][ni][1] + b0);
            outS[(jrow + 8) * 132 + tcol]     = expf(acc[mi][ni][2] + b8);
            outS[(jrow + 8) * 132 + tcol + 1] = expf(acc[mi][ni][3] + b8);
        }
    __syncthreads();

    for (int i = tid; i < 128 * 32; i += 256) {
        int r = i >> 5, q = i & 31;
        int d = d0 + r;
        int rr = rt0 + q * 4;
        int b = rr / Tdim, t = rr - b * Tdim;
        if (d < XDdim)
            *(float4*)&y_out[((size_t)b * XDdim + d) * Tdim + t] =
                *(float4*)&outS[r * 132 + q * 4];
    }
}

// ============== K1h2: h2 = tanh(Wzx2 @ h1 + bzx2) (unchanged) ==============
__global__ __launch_bounds__(256, 2) void h2gemm_kernel(const float* __restrict__ bzx2) {
    extern __shared__ char sm[];
    const uint32_t smb = smem_u32(sm);
    const int tid = threadIdx.x, lane = tid & 31, w = tid >> 5;
    const int rt0 = blockIdx.y * 128;

    float* biasS = (float*)(sm + 81920);
    if (tid < 128) biasS[tid] = bzx2[tid];

    const int rowE = tid >> 2, rowO = 64 + (tid >> 2);
    const int rrE = rt0 + rowE, rrO = rt0 + rowO;
    const int bE = rrE / Tdim, tE = rrE - bE * Tdim;
    const int bO = rrO / Tdim, tO = rrO - bO * Tdim;
    const size_t boffE = ((size_t)bE * TPAD + tE) * Hdim;
    const size_t boffO = ((size_t)bO * TPAD + tO) * Hdim;

    auto load_stage = [&](int st, int dk) {
        uint32_t base = smb + st * STG2;
#pragma unroll
        for (int i = 0; i < 8; ++i) {
            int rem = (i & 1) * 256 + tid;
            int row = rem >> 2, seg = rem & 3;
            const __nv_bfloat16* src;
            if (i < 4) {
                const __nv_bfloat16* M = (i < 2) ? d_zx2h : d_zx2l;
                src = M + (size_t)row * Hdim + dk * 32 + seg * 8;
            } else {
                const __nv_bfloat16* M = (i < 6) ? d_h1h : d_h1l;
                src = M + ((i & 1) ? boffO : boffE) + dk * 32 + seg * 8;
            }
            cpa16(base + (i >> 1) * 10240 + row * ROWB + seg * 16, src, 16);
        }
        CP_COMMIT();
    };

    float acc[4][4][4];
#pragma unroll
    for (int mi = 0; mi < 4; ++mi)
#pragma unroll
        for (int ni = 0; ni < 4; ++ni)
#pragma unroll
            for (int q = 0; q < 4; ++q) acc[mi][ni][q] = 0.f;

    const int m0 = (w >> 2) * 64, n0 = (w & 3) * 32;
    const uint32_t partA = ((lane & 7) + ((lane >> 3) & 1) * 8) * ROWB + ((lane >> 4) & 1) * 16;
    const uint32_t partB = (((lane >> 4) & 1) * 8 + (lane & 7)) * ROWB + ((lane >> 3) & 1) * 16;

    load_stage(0, 0);
    int st = 0;

    for (int c = 0; c < 4; ++c) {
        if (c < 3) { load_stage(st ^ 1, c + 1); CP_WAIT1(); }
        else       { CP_WAIT0(); }
        __syncthreads();

        uint32_t sah = smb + st * STG2 + m0 * ROWB;
        uint32_t sal = sah + 10240;
        uint32_t sbh = smb + st * STG2 + 20480 + n0 * ROWB;
        uint32_t sbl = sbh + 10240;
#pragma unroll
        for (int k16 = 0; k16 < 2; ++k16) {
            uint32_t bh[2][4], bl[2][4], af[4][4];
#pragma unroll
            for (int np = 0; np < 2; ++np) {
                LDSM4(bh[np], sbh + np * 16 * ROWB + k16 * 32 + partB);
                LDSM4(bl[np], sbl + np * 16 * ROWB + k16 * 32 + partB);
            }
#pragma unroll
            for (int mi = 0; mi < 4; ++mi)
                LDSM4(af[mi], sah + mi * 16 * ROWB + k16 * 32 + partA);
#pragma unroll
            for (int mi = 0; mi < 4; ++mi)
#pragma unroll
                for (int ni = 0; ni < 4; ++ni) {
                    MMA16816(acc[mi][ni], af[mi], bh[ni >> 1][(ni & 1) * 2],
                             bh[ni >> 1][(ni & 1) * 2 + 1]);
                    MMA16816(acc[mi][ni], af[mi], bl[ni >> 1][(ni & 1) * 2],
                             bl[ni >> 1][(ni & 1) * 2 + 1]);
                }
#pragma unroll
            for (int mi = 0; mi < 4; ++mi)
                LDSM4(af[mi], sal + mi * 16 * ROWB + k16 * 32 + partA);
#pragma unroll
            for (int mi = 0; mi < 4; ++mi)
#pragma unroll
                for (int ni = 0; ni < 4; ++ni)
                    MMA16816(acc[mi][ni], af[mi], bh[ni >> 1][(ni & 1) * 2],
                             bh[ni >> 1][(ni & 1) * 2 + 1]);
        }
        __syncthreads();
        st ^= 1;
    }

    float* outS = (float*)sm;
    const int gid = lane >> 2, tq = lane & 3;
#pragma unroll
    for (int mi = 0; mi < 4; ++mi)
#pragma unroll
        for (int ni = 0; ni < 4; ++ni) {
            int jrow = m0 + 16 * mi + gid;
            int tcol = n0 + 8 * ni + tq * 2;
            float b0 = biasS[jrow], b8 = biasS[jrow + 8];
            outS[tcol * 132 + jrow]           = tanhfast(acc[mi][ni][0] + b0);
            outS[(tcol + 1) * 132 + jrow]     = tanhfast(acc[mi][ni][1] + b0);
            outS[tcol * 132 + jrow + 8]       = tanhfast(acc[mi][ni][2] + b8);
            outS[(tcol + 1) * 132 + jrow + 8] = tanhfast(acc[mi][ni][3] + b8);
        }
    __syncthreads();

    for (int i = tid; i < 128 * 32; i += 256) {
        int r = i >> 5, q = i & 31;
        int rr = rt0 + r;
        int b = rr / Tdim, t = rr - b * Tdim;
        float4 v = *(float4*)&outS[r * 132 + q * 4];
        __nv_bfloat162 h01, h23, l01, l23;
        h01.x = __float2bfloat16(v.x); h01.y = __float2bfloat16(v.y);
        h23.x = __float2bfloat16(v.z); h23.y = __float2bfloat16(v.w);
        l01.x = __float2bfloat16(v.x - __bfloat162float(h01.x));
        l01.y = __float2bfloat16(v.y - __bfloat162float(h01.y));
        l23.x = __float2bfloat16(v.z - __bfloat162float(h23.x));
        l23.y = __float2bfloat16(v.w - __bfloat162float(h23.y));
        size_t base = ((size_t)b * TPAD + t) * Hdim + q * 4;
        *(__nv_bfloat162*)&d_h2h[base]     = h01;
        *(__nv_bfloat162*)&d_h2h[base + 2] = h23;
        *(__nv_bfloat162*)&d_h2l[base]     = l01;
        *(__nv_bfloat162*)&d_h2l[base + 2] = l23;
    }
}

// ============== K2: LSTM — gates-in-M layout, zero M-waste ==============
// D[gates, rows]: M = gates (32/warp, 2 tiles of 16), N = 8 batch rows.
// A = permuted Wsm (register-resident frags), B = h tile via non-trans ldmatrix.
// 32 blocks x 8 rows; 16 mma + 4 ldsm per warp per step.
#define LSTM_SMEM3 (139264 + 2 * 4352)
#define WROW 272
__global__ __launch_bounds__(512, 1) void lstm_mma_kernel(const float* __restrict__ Whh) {
    extern __shared__ char sm[];
    __nv_bfloat16* Wsm = (__nv_bfloat16*)sm;                 // [512][136] permuted
    __nv_bfloat16* hAbuf[2] = {(__nv_bfloat16*)(sm + 139264),
                               (__nv_bfloat16*)(sm + 139264 + 4352)};  // [8][136] each

    const int tid = threadIdx.x, lane = tid & 31, w = tid >> 5;
    const int b0 = blockIdx.x * 8;

    // permuted W: row (hblk*32 + q*8 + hsub) = gate (q*128 + hblk*8 + hsub)
    for (int idx = tid; idx < G4 * Hdim; idx += 512) {
        int g = idx >> 7, k = idx & 127;
        int q = g >> 7;
        int j = g & 127;
        int pr = (j >> 3) * 32 + q * 8 + (j & 7);
        Wsm[pr * 136 + k] = __float2bfloat16(Whh[idx]);
    }
    for (int idx = tid; idx < 2 * 8 * 136; idx += 512)
        ((__nv_bfloat16*)(sm + 139264))[idx] = __float2bfloat16(0.f);
    __syncthreads();

    // resident A frags: aw[mt*8 + kc]
    uint32_t aw[16][4];
    const uint32_t partA = ((lane & 7) + ((lane >> 3) & 1) * 8) * WROW + ((lane >> 4) & 1) * 16;
    {
        uint32_t wbase = smem_u32(Wsm) + (w * 32) * WROW;
#pragma unroll
        for (int mt = 0; mt < 2; ++mt)
#pragma unroll
            for (int kc = 0; kc < 8; ++kc)
                LDSM4(aw[mt * 8 + kc], wbase + mt * 16 * WROW + kc * 32 + partA);
    }

    // B frag addressing: lanes 0-7 rows@+0B, 8-15 @+16B, 16-23 @+32B, 24-31 @+48B
    const uint32_t partBh = (uint32_t)(lane & 7) * WROW + (uint32_t)(lane >> 3) * 16;

    const int hsub = lane >> 2;          // 0..7
    const int r0 = 2 * (lane & 3);       // 0,2,4,6
    const int hdim = w * 8 + hsub;       // this lane's h index

    // pf[qt*2 + rs] = P[b0 + r0 + rs][qt*128 + hdim]
    float pf[8];
#pragma unroll
    for (int qt = 0; qt < 4; ++qt)
#pragma unroll
        for (int rs = 0; rs < 2; ++rs)
            pf[qt * 2 + rs] =
                d_P[((size_t)(Tdim - 1) * Bdim + b0 + r0 + rs) * G4 + qt * 128 + hdim];

    float cc0 = 0.f, cc1 = 0.f;
    int cur = 0;

    for (int t = Tdim - 1; t >= 0; --t) {
        // acc[mt][q]: gate type qt = mt*2 + (q>=2), row = r0 + (q&1)
        float acc[2][4];
        acc[0][0] = pf[0]; acc[0][1] = pf[1];   // i
        acc[0][2] = pf[2]; acc[0][3] = pf[3];   // f
        acc[1][0] = pf[4]; acc[1][1] = pf[5];   // g
        acc[1][2] = pf[6]; acc[1][3] = pf[7];   // o
        if (t > 0) {
#pragma unroll
            for (int qt = 0; qt < 4; ++qt)
#pragma unroll
                for (int rs = 0; rs < 2; ++rs)
                    pf[qt * 2 + rs] =
                        d_P[((size_t)(t - 1) * Bdim + b0 + r0 + rs) * G4 + qt * 128 + hdim];
        }

        const uint32_t habase = smem_u32(hAbuf[cur]);
#pragma unroll
        for (int kc2 = 0; kc2 < 4; ++kc2) {
            uint32_t bf[4];
            LDSM4(bf, habase + kc2 * 64 + partBh);
            MMA16816(acc[0], aw[2 * kc2],     bf[0], bf[1]);
            MMA16816(acc[1], aw[8 + 2 * kc2], bf[0], bf[1]);
            MMA16816(acc[0], aw[2 * kc2 + 1],     bf[2], bf[3]);
            MMA16816(acc[1], aw[8 + 2 * kc2 + 1], bf[2], bf[3]);
        }

        // in-lane LSTM update for rows r0, r0+1 at h = hdim
        cc0 = sig_hw(acc[0][2]) * cc0 + sig_hw(acc[0][0]) * tanh_hw(acc[1][0]);
        float h0 = sig_hw(acc[1][2]) * tanh_hw(cc0);
        cc1 = sig_hw(acc[0][3]) * cc1 + sig_hw(acc[0][1]) * tanh_hw(acc[1][1]);
        float h1 = sig_hw(acc[1][3]) * tanh_hw(cc1);

        hAbuf[cur ^ 1][r0 * 136 + hdim]       = __float2bfloat16(h0);
        hAbuf[cur ^ 1][(r0 + 1) * 136 + hdim] = __float2bfloat16(h1);
        d_G[((size_t)t * Bdim + b0 + r0) * Hdim + hdim]     = h0;
        d_G[((size_t)t * Bdim + b0 + r0 + 1) * Hdim + hdim] = h1;
        __syncthreads();
        cur ^= 1;
    }
}

// ============== K3: inference scan (unchanged) ==============
__global__ __launch_bounds__(128) void infer_kernel(
    const float* __restrict__ eps,
    const float* __restrict__ Wzz, const float* __restrict__ bzz,
    const float* __restrict__ Wim, const float* __restrict__ bim,
    const float* __restrict__ Wil, const float* __restrict__ bil,
    float* __restrict__ zm_out, float* __restrict__ zl_out) {
    __shared__ float Wzzs[16 * 128];
    __shared__ float Wims[128 * 16];
    __shared__ float Wils[128 * 16];
    __shared__ float zsm[16];
    __shared__ float gts[128];
    __shared__ float pm_s[8][16], pl_s[8][16];

    const int tid = threadIdx.x;
    const int b = blockIdx.x;

    for (int idx = tid; idx < 2048; idx += 128) {
        { int j = idx >> 4, k = idx & 15; Wzzs[k * 128 + j] = Wzz[idx]; }
        { int m = idx >> 7, j = idx & 127;
          Wims[j * 16 + m] = Wim[idx]; Wils[j * 16 + m] = Wil[idx]; }
    }
    if (tid < 16) zsm[tid] = 0.f;
    float bzzr = bzz[tid];
    float bimr = 0.f, bilr = 0.f;
    if (tid < 16) { bimr = bim[tid]; bilr = bil[tid]; }
    __syncthreads();

    const int m = tid & 15, part = tid >> 4;
    for (int t = 0; t < Tdim; ++t) {
        {
            float s = bzzr;
#pragma unroll
            for (int k = 0; k < 16; ++k) s += zsm[k] * Wzzs[k * 128 + tid];
            float g = d_G[(size_t)t * Bdim * Hdim + (size_t)b * Hdim + tid];
            gts[tid] = 0.5f * (tanhf(s) + g);
        }
        __syncthreads();
        {
            float sm2 = 0.f, sl2 = 0.f;
            int jb = part * 16;
#pragma unroll
            for (int k = 0; k < 16; ++k) {
                float g = gts[jb + k];
                sm2 += g * Wims[(jb + k) * 16 + m];
                sl2 += g * Wils[(jb + k) * 16 + m];
            }
            pm_s[part][m] = sm2; pl_s[part][m] = sl2;
        }
        __syncthreads();
        if (tid < 16) {
            float mean = bimr, lv = bilr;
#pragma unroll
            for (int p = 0; p < 8; ++p) { mean += pm_s[p][tid]; lv += pl_s[p][tid]; }
            int o = t * Bdim * ZDdim + b * ZDdim + tid;
            float e = eps[o];
            float z = mean + e * expf(0.5f * lv);
            zsm[tid] = z;
            zm_out[o] = mean; zl_out[o] = lv; d_Z[o] = z;
        }
        __syncthreads();
    }
}

// ============== K4: generation small part (stops at h1, unchanged) ==============
#define GEN_SMEM ((512 + 2048 + 1536 + 2048) * 4)
__global__ __launch_bounds__(256) void gen_kernel(
    const float* __restrict__ Wg1, const float* __restrict__ bg1,
    const float* __restrict__ Wg2, const float* __restrict__ bg2,
    const float* __restrict__ Wp1, const float* __restrict__ bp1,
    const float* __restrict__ Wp2, const float* __restrict__ bp2,
    const float* __restrict__ Wpm, const float* __restrict__ bpm,
    const float* __restrict__ Wpl, const float* __restrict__ bpl,
    const float* __restrict__ Wzx1, const float* __restrict__ bzx1,
    float* __restrict__ zmp_out, float* __restrict__ zlp_out,
    float* __restrict__ zo_out) {
    extern __shared__ char sm[];
    float* smf = (float*)sm;
    float* zrow  = smf;
    float* Wzx1s = zrow + 512;
    float* sw    = Wzx1s + 2048;
    float* a1s   = sw + 1536;
    float* p1s   = a1s + 512;
    float* zps   = p1s + 512;
    float* gts   = zps + 512;

    const int tid = threadIdx.x;
    const int b = blockIdx.y;
    const int t0 = blockIdx.x * 32;
    const int nrows = min(32, Tdim - t0);

    for (int idx = tid; idx < 2048; idx += 256) {
        int j = idx >> 4, k = idx & 15;
        Wzx1s[k * 128 + j] = Wzx1[idx];
    }
    if (tid < 256) {
        sw[tid] = Wg1[tid]; sw[256 + tid] = Wg2[tid]; sw[512 + tid] = Wp1[tid];
        sw[768 + tid] = Wp2[tid]; sw[1024 + tid] = Wpm[tid]; sw[1280 + tid] = Wpl[tid];
    }
    for (int idx = tid; idx < 512; idx += 256) {
        int r = idx >> 4, m = idx & 15;
        zrow[idx] = (r < nrows) ? d_Z[(size_t)(t0 + r) * Bdim * ZDdim + b * ZDdim + m] : 0.f;
    }
    __syncthreads();

    for (int idx = tid; idx < 512; idx += 256) {
        int r = idx & 31, k = idx >> 5;
        if (r < nrows)
            zo_out[(size_t)b * ZDdim * Tdim + (size_t)k * Tdim + t0 + r] = zrow[r * 16 + k];
    }

    for (int idx = tid; idx < 512; idx += 256) {
        int r = idx >> 4, m = idx & 15;
        float s1 = bg1[m], s2 = bp1[m];
#pragma unroll
        for (int k = 0; k < 16; ++k) {
            float z = zrow[r * 16 + k];
            s1 += z * sw[m * 16 + k];
            s2 += z * sw[512 + m * 16 + k];
        }
        a1s[idx] = fmaxf(s1, 0.f);
        p1s[idx] = fmaxf(s2, 0.f);
    }
    __syncthreads();
    for (int idx = tid; idx < 512; idx += 256) {
        int r = idx >> 4, m = idx & 15;
        float s1 = bg2[m], s2 = bp2[m];
#pragma unroll
        for (int k = 0; k < 16; ++k) {
            s1 += a1s[r * 16 + k] * sw[256 + m * 16 + k];
            s2 += p1s[r * 16 + k] * sw[768 + m * 16 + k];
        }
        gts[idx] = sigm(s1);
        zps[idx] = s2;
    }
    __syncthreads();
    for (int idx = tid; idx < 512; idx += 256) {
        int r = idx >> 4, m = idx & 15;
        float pm = bpm[m], pl = bpl[m];
#pragma unroll
        for (int k = 0; k < 16; ++k) {
            float z = zrow[r * 16 + k];
            pm += z * sw[1024 + m * 16 + k];
            pl += fmaxf(zps[r * 16 + k], 0.f) * sw[1280 + m * 16 + k];
        }
        float gate = gts[idx];
        float zmp = (1.f - gate) * pm + gate * zps[idx];
        float sp = (pl > 20.f) ? pl : log1pf(expf(pl));
        float zlp = logf(sp);
        if (r < nrows) {
            int o = (t0 + r) * Bdim * ZDdim + b * ZDdim + m;
            zmp_out[o] = zmp; zlp_out[o] = zlp;
        }
    }

    for (int idx = tid; idx < 4096; idx += 256) {
        int r = idx >> 7, j = idx & 127;
        if (r < nrows) {
            float s = bzx1[j];
#pragma unroll
            for (int k = 0; k < 16; ++k) s += zrow[r * 16 + k] * Wzx1s[k * 128 + j];
            float v = tanhf(s);
            __nv_bfloat16 h = __float2bfloat16(v);
            __nv_bfloat16 l = __float2bfloat16(v - __bfloat162float(h));
            size_t o = ((size_t)b * TPAD + t0 + r) * Hdim + j;
            d_h1h[o] = h; d_h1l[o] = l;
        }
    }
}

// =====================================================================
extern "C" void kernel_launch(void* const* d_in, const int* in_sizes, int n_in,
                              void* d_out, int out_size) {
    const float* x    = (const float*)d_in[0];
    const float* eps  = (const float*)d_in[1];
    const float* Wih  = (const float*)d_in[2];
    const float* Whh  = (const float*)d_in[3];
    const float* bih  = (const float*)d_in[4];
    const float* bhh  = (const float*)d_in[5];
    const float* Wzz  = (const float*)d_in[6];
    const float* bzz  = (const float*)d_in[7];
    const float* Wim  = (const float*)d_in[8];
    const float* bim  = (const float*)d_in[9];
    const float* Wil  = (const float*)d_in[10];
    const float* bil  = (const float*)d_in[11];
    const float* Wg1  = (const float*)d_in[12];
    const float* bg1  = (const float*)d_in[13];
    const float* Wg2  = (const float*)d_in[14];
    const float* bg2  = (const float*)d_in[15];
    const float* Wp1  = (const float*)d_in[16];
    const float* bp1  = (const float*)d_in[17];
    const float* Wp2  = (const float*)d_in[18];
    const float* bp2  = (const float*)d_in[19];
    const float* Wpm  = (const float*)d_in[20];
    const float* bpm  = (const float*)d_in[21];
    const float* Wpl  = (const float*)d_in[22];
    const float* bpl  = (const float*)d_in[23];
    const float* Wzx1 = (const float*)d_in[24];
    const float* bzx1 = (const float*)d_in[25];
    const float* Wzx2 = (const float*)d_in[26];
    const float* bzx2 = (const float*)d_in[27];
    const float* Wgy  = (const float*)d_in[28];
    const float* bgy  = (const float*)d_in[29];

    float* out = (float*)d_out;
    float* y_out   = out;
    float* zm_out  = out + 39398400;
    float* zl_out  = out + 40627200;
    float* zmp_out = out + 41856000;
    float* zlp_out = out + 43084800;
    float* zo_out  = out + 44313600;

    cudaFuncSetAttribute(gemm_mma_kernel, cudaFuncAttributeMaxDynamicSharedMemorySize, MMA_SMEM2);
    cudaFuncSetAttribute(ygemm_kernel, cudaFuncAttributeMaxDynamicSharedMemorySize, MMA_SMEM2);
    cudaFuncSetAttribute(h2gemm_kernel, cudaFuncAttributeMaxDynamicSharedMemorySize, MMA_SMEM2);
    cudaFuncSetAttribute(lstm_mma_kernel, cudaFuncAttributeMaxDynamicSharedMemorySize, LSTM_SMEM3);
    cudaFuncSetAttribute(gen_kernel,  cudaFuncAttributeMaxDynamicSharedMemorySize, GEN_SMEM);

    convert_x_kernel<<<dim3(170, Bdim), 256>>>(x);
    convert_w_kernel<<<(G4 * XDpad + 255) / 256, 256>>>(Wih);
    convert_gy_kernel<<<(640 * Hdim + 255) / 256, 256>>>(Wgy);
    convert_zx2_kernel<<<(Hdim * Hdim + 255) / 256, 256>>>(Wzx2);
    gemm_mma_kernel<<<dim3(4, NROWS / 128), 256, MMA_SMEM2>>>(bih, bhh);
    lstm_mma_kernel<<<32, 512, LSTM_SMEM3>>>(Whh);
    infer_kernel<<<256, 128>>>(eps, Wzz, bzz, Wim, bim, Wil, bil, zm_out, zl_out);
    gen_kernel<<<dim3(10, Bdim), 256, GEN_SMEM>>>(
        Wg1, bg1, Wg2, bg2, Wp1, bp1, Wp2, bp2, Wpm, bpm, Wpl, bpl,
        Wzx1, bzx1, zmp_out, zlp_out, zo_out);
    h2gemm_kernel<<<dim3(1, NROWS / 128), 256, MMA_SMEM2>>>(bzx2);
    ygemm_kernel<<<dim3(5, NROWS / 128), 256, MMA_SMEM2>>>(bgy, y_out);
}

// round 17
// speedup vs baseline: 1.1108x; 1.1108x over previous
#include <cuda_runtime.h>
#include <cuda_bf16.h>
#include <math.h>
#include <stdint.h>

#define Bdim 256
#define Tdim 300
#define XDdim 513
#define XDpad 544
#define Hdim 128
#define G4 512
#define ZDdim 16
#define TPAD 384
#define NROWS (Bdim * Tdim)

__device__ float d_P[Tdim * Bdim * G4];
__device__ float d_G[Tdim * Bdim * Hdim];
__device__ float d_Z[Tdim * Bdim * ZDdim];
__device__ __nv_bfloat16 d_xh[(size_t)Bdim * Tdim * XDpad];
__device__ __nv_bfloat16 d_Wh[G4 * XDpad];
__device__ __nv_bfloat16 d_Wl[G4 * XDpad];
__device__ __nv_bfloat16 d_h1h[(size_t)Bdim * TPAD * Hdim];
__device__ __nv_bfloat16 d_h1l[(size_t)Bdim * TPAD * Hdim];
__device__ __nv_bfloat16 d_h2h[(size_t)Bdim * TPAD * Hdim];
__device__ __nv_bfloat16 d_h2l[(size_t)Bdim * TPAD * Hdim];
__device__ __nv_bfloat16 d_gyh[640 * Hdim];
__device__ __nv_bfloat16 d_gyl[640 * Hdim];
__device__ __nv_bfloat16 d_zx2h[Hdim * Hdim];
__device__ __nv_bfloat16 d_zx2l[Hdim * Hdim];

__device__ __forceinline__ float sigm(float x) { return 1.f / (1.f + expf(-x)); }
__device__ __forceinline__ float tanh_hw(float x) {
    float r;
    asm("tanh.approx.f32 %0, %1;" : "=f"(r) : "f"(x));
    return r;
}
__device__ __forceinline__ float sig_hw(float x) {
    return fmaf(0.5f, tanh_hw(0.5f * x), 0.5f);
}
__device__ __forceinline__ float tanhfast(float x) {
    return 1.f - __fdividef(2.f, __expf(2.f * x) + 1.f);
}

__device__ __forceinline__ uint32_t smem_u32(const void* p) {
    uint32_t a;
    asm("{ .reg .u64 tmp; cvta.to.shared.u64 tmp, %1; cvt.u32.u64 %0, tmp; }"
        : "=r"(a) : "l"(p));
    return a;
}
__device__ __forceinline__ void cpa16(uint32_t dst, const void* src, int valid) {
    asm volatile("cp.async.ca.shared.global [%0], [%1], 16, %2;"
                 :: "r"(dst), "l"(__cvta_generic_to_global(src)), "r"(valid) : "memory");
}
#define CP_COMMIT() asm volatile("cp.async.commit_group;" ::: "memory")
#define CP_WAIT1()  asm volatile("cp.async.wait_group 1;" ::: "memory")
#define CP_WAIT0()  asm volatile("cp.async.wait_group 0;" ::: "memory")
#define LDSM4(r, addr)                                                           \
    asm volatile("ldmatrix.sync.aligned.m8n8.x4.shared.b16 {%0,%1,%2,%3}, [%4];" \
                 : "=r"((r)[0]), "=r"((r)[1]), "=r"((r)[2]), "=r"((r)[3]) : "r"(addr))
#define MMA16816(d, a, b0v, b1v)                                                 \
    asm volatile("mma.sync.aligned.m16n8k16.row.col.f32.bf16.bf16.f32 "          \
                 "{%0,%1,%2,%3}, {%4,%5,%6,%7}, {%8,%9}, {%0,%1,%2,%3};"         \
                 : "+f"((d)[0]), "+f"((d)[1]), "+f"((d)[2]), "+f"((d)[3])        \
                 : "r"((a)[0]), "r"((a)[1]), "r"((a)[2]), "r"((a)[3]),           \
                   "r"(b0v), "r"(b1v))

// ============== K0a: x transpose -> bf16 hi only ==============
__global__ __launch_bounds__(256) void convert_x_kernel(const float* __restrict__ x) {
    __shared__ float tileS[32][33];
    const int dt = blockIdx.x % 17, tt = blockIdx.x / 17;
    const int b = blockIdx.y;
    const int d0 = dt * 32, t0 = tt * 32;
    const int r0 = threadIdx.x >> 5, c = threadIdx.x & 31;
#pragma unroll
    for (int i = 0; i < 4; ++i) {
        int d = d0 + r0 + i * 8, t = t0 + c;
        float v = 0.f;
        if (d < XDdim && t < Tdim) v = x[((size_t)b * XDdim + d) * Tdim + t];
        tileS[r0 + i * 8][c] = v;
    }
    __syncthreads();
#pragma unroll
    for (int i = 0; i < 4; ++i) {
        int trow = t0 + r0 + i * 8, d = d0 + c;
        if (trow < Tdim) {
            float v = tileS[c][r0 + i * 8];
            d_xh[((size_t)b * Tdim + trow) * XDpad + d] = __float2bfloat16(v);
        }
    }
}

// ============== K0b: Wih split ==============
__global__ __launch_bounds__(256) void convert_w_kernel(const float* __restrict__ W) {
    int idx = blockIdx.x * 256 + threadIdx.x;
    if (idx >= G4 * XDpad) return;
    int d = idx % XDpad, j = idx / XDpad;
    float v = (d < XDdim) ? W[(size_t)j * XDdim + d] : 0.f;
    __nv_bfloat16 h = __float2bfloat16(v);
    __nv_bfloat16 l = __float2bfloat16(v - __bfloat162float(h));
    d_Wh[idx] = h; d_Wl[idx] = l;
}

// ============== K0c: Wgy split ==============
__global__ __launch_bounds__(256) void convert_gy_kernel(const float* __restrict__ W) {
    int idx = blockIdx.x * 256 + threadIdx.x;
    if (idx >= 640 * Hdim) return;
    int d = idx >> 7;
    float v = (d < XDdim) ? W[idx] : 0.f;
    __nv_bfloat16 h = __float2bfloat16(v);
    __nv_bfloat16 l = __float2bfloat16(v - __bfloat162float(h));
    d_gyh[idx] = h; d_gyl[idx] = l;
}

// ============== K0d: Wzx2 split (128x128) ==============
__global__ __launch_bounds__(256) void convert_zx2_kernel(const float* __restrict__ W) {
    int idx = blockIdx.x * 256 + threadIdx.x;
    if (idx >= Hdim * Hdim) return;
    float v = W[idx];
    __nv_bfloat16 h = __float2bfloat16(v);
    __nv_bfloat16 l = __float2bfloat16(v - __bfloat162float(h));
    d_zx2h[idx] = h; d_zx2l[idx] = l;
}

// ============== K1: two-term HMMA GEMM (Ah*Bh + Al*Bh) ==============
#define ROWB 80
#define STG3 30720
#define MMA_SMEM3 (67584 + 512)
#define STG2 40960
#define MMA_SMEM2 (81920 + 512)
#define NCHUNK2 17

__global__ __launch_bounds__(256, 2) void gemm_mma_kernel(
    const float* __restrict__ bih, const float* __restrict__ bhh) {
    extern __shared__ char sm[];
    const uint32_t smb = smem_u32(sm);
    const int tid = threadIdx.x, lane = tid & 31, w = tid >> 5;
    const int j0 = blockIdx.x * 128;
    const int rt0 = blockIdx.y * 128;

    float* biasS = (float*)(sm + 67584);
    if (tid < 128) biasS[tid] = bih[j0 + tid] + bhh[j0 + tid];

    auto load_stage = [&](int st, int dk) {
        uint32_t base = smb + st * STG3;
#pragma unroll
        for (int i = 0; i < 6; ++i) {
            const __nv_bfloat16* M = (i < 2) ? d_Wh : (i < 4) ? d_Wl : d_xh;
            int rem = (i & 1) * 256 + tid;
            int row = rem >> 2, seg = rem & 3;
            size_t go = (i < 4)
                ? ((size_t)(j0 + row) * XDpad + dk * 32 + seg * 8)
                : ((size_t)(rt0 + row) * XDpad + dk * 32 + seg * 8);
            cpa16(base + (i >> 1) * 10240 + row * ROWB + seg * 16, M + go, 16);
        }
        CP_COMMIT();
    };

    float acc[4][4][4];
#pragma unroll
    for (int mi = 0; mi < 4; ++mi)
#pragma unroll
        for (int ni = 0; ni < 4; ++ni)
#pragma unroll
            for (int q = 0; q < 4; ++q) acc[mi][ni][q] = 0.f;

    const int m0 = (w >> 2) * 64, n0 = (w & 3) * 32;
    const uint32_t partA = ((lane & 7) + ((lane >> 3) & 1) * 8) * ROWB + ((lane >> 4) & 1) * 16;
    const uint32_t partB = (((lane >> 4) & 1) * 8 + (lane & 7)) * ROWB + ((lane >> 3) & 1) * 16;

    load_stage(0, 0);
    int st = 0;

    for (int c = 0; c < NCHUNK2; ++c) {
        if (c < NCHUNK2 - 1) { load_stage(st ^ 1, c + 1); CP_WAIT1(); }
        else                 { CP_WAIT0(); }
        __syncthreads();

        uint32_t sah = smb + st * STG3 + m0 * ROWB;
        uint32_t sal = sah + 10240;
        uint32_t sbh = smb + st * STG3 + 20480 + n0 * ROWB;
#pragma unroll
        for (int k16 = 0; k16 < 2; ++k16) {
            uint32_t bh[2][4], af[4][4];
#pragma unroll
            for (int np = 0; np < 2; ++np)
                LDSM4(bh[np], sbh + np * 16 * ROWB + k16 * 32 + partB);
#pragma unroll
            for (int mi = 0; mi < 4; ++mi)
                LDSM4(af[mi], sah + mi * 16 * ROWB + k16 * 32 + partA);
#pragma unroll
            for (int mi = 0; mi < 4; ++mi)
#pragma unroll
                for (int ni = 0; ni < 4; ++ni)
                    MMA16816(acc[mi][ni], af[mi], bh[ni >> 1][(ni & 1) * 2],
                             bh[ni >> 1][(ni & 1) * 2 + 1]);
#pragma unroll
            for (int mi = 0; mi < 4; ++mi)
                LDSM4(af[mi], sal + mi * 16 * ROWB + k16 * 32 + partA);
#pragma unroll
            for (int mi = 0; mi < 4; ++mi)
#pragma unroll
                for (int ni = 0; ni < 4; ++ni)
                    MMA16816(acc[mi][ni], af[mi], bh[ni >> 1][(ni & 1) * 2],
                             bh[ni >> 1][(ni & 1) * 2 + 1]);
        }
        __syncthreads();
        st ^= 1;
    }

    float* outS = (float*)sm;
    const int gid = lane >> 2, tq = lane & 3;
#pragma unroll
    for (int mi = 0; mi < 4; ++mi)
#pragma unroll
        for (int ni = 0; ni < 4; ++ni) {
            int jrow = m0 + 16 * mi + gid;
            int tcol = n0 + 8 * ni + tq * 2;
            outS[tcol * 132 + jrow]           = acc[mi][ni][0];
            outS[(tcol + 1) * 132 + jrow]     = acc[mi][ni][1];
            outS[tcol * 132 + jrow + 8]       = acc[mi][ni][2];
            outS[(tcol + 1) * 132 + jrow + 8] = acc[mi][ni][3];
        }
    __syncthreads();

    for (int i = tid; i < 128 * 32; i += 256) {
        int r = i >> 5, q = i & 31;
        int rr = rt0 + r;
        int b = rr / Tdim, t = rr - b * Tdim;
        float4 v = *(float4*)&outS[r * 132 + q * 4];
        float4 bb = *(float4*)&biasS[q * 4];
        v.x += bb.x; v.y += bb.y; v.z += bb.z; v.w += bb.w;
        *(float4*)&d_P[((size_t)t * Bdim + b) * G4 + j0 + q * 4] = v;
    }
}

// ============== K1y: y = exp(Wgy @ h2 + bgy), 3 terms (unchanged) ==============
#define NCHUNK_Y2 4
__global__ __launch_bounds__(256, 2) void ygemm_kernel(
    const float* __restrict__ bgy, float* __restrict__ y_out) {
    extern __shared__ char sm[];
    const uint32_t smb = smem_u32(sm);
    const int tid = threadIdx.x, lane = tid & 31, w = tid >> 5;
    const int d0 = blockIdx.x * 128;
    const int rt0 = blockIdx.y * 128;

    float* biasS = (float*)(sm + 81920);
    if (tid < 128) biasS[tid] = (d0 + tid < XDdim) ? bgy[d0 + tid] : 0.f;

    const int rowE = tid >> 2, rowO = 64 + (tid >> 2);
    const int rrE = rt0 + rowE, rrO = rt0 + rowO;
    const int bE = rrE / Tdim, tE = rrE - bE * Tdim;
    const int bO = rrO / Tdim, tO = rrO - bO * Tdim;
    const size_t boffE = ((size_t)bE * TPAD + tE) * Hdim;
    const size_t boffO = ((size_t)bO * TPAD + tO) * Hdim;

    auto load_stage = [&](int st, int dk) {
        uint32_t base = smb + st * STG2;
#pragma unroll
        for (int i = 0; i < 8; ++i) {
            int rem = (i & 1) * 256 + tid;
            int row = rem >> 2, seg = rem & 3;
            const __nv_bfloat16* src;
            if (i < 4) {
                const __nv_bfloat16* M = (i < 2) ? d_gyh : d_gyl;
                src = M + (size_t)(d0 + row) * Hdim + dk * 32 + seg * 8;
            } else {
                const __nv_bfloat16* M = (i < 6) ? d_h2h : d_h2l;
                src = M + ((i & 1) ? boffO : boffE) + dk * 32 + seg * 8;
            }
            cpa16(base + (i >> 1) * 10240 + row * ROWB + seg * 16, src, 16);
        }
        CP_COMMIT();
    };

    float acc[4][4][4];
#pragma unroll
    for (int mi = 0; mi < 4; ++mi)
#pragma unroll
        for (int ni = 0; ni < 4; ++ni)
#pragma unroll
            for (int q = 0; q < 4; ++q) acc[mi][ni][q] = 0.f;

    const int m0 = (w >> 2) * 64, n0 = (w & 3) * 32;
    const uint32_t partA = ((lane & 7) + ((lane >> 3) & 1) * 8) * ROWB + ((lane >> 4) & 1) * 16;
    const uint32_t partB = (((lane >> 4) & 1) * 8 + (lane & 7)) * ROWB + ((lane >> 3) & 1) * 16;

    load_stage(0, 0);
    int st = 0;

    for (int c = 0; c < NCHUNK_Y2; ++c) {
        if (c < NCHUNK_Y2 - 1) { load_stage(st ^ 1, c + 1); CP_WAIT1(); }
        else                   { CP_WAIT0(); }
        __syncthreads();

        uint32_t sah = smb + st * STG2 + m0 * ROWB;
        uint32_t sal = sah + 10240;
        uint32_t sbh = smb + st * STG2 + 20480 + n0 * ROWB;
        uint32_t sbl = sbh + 10240;
#pragma unroll
        for (int k16 = 0; k16 < 2; ++k16) {
            uint32_t bh[2][4], bl[2][4], af[4][4];
#pragma unroll
            for (int np = 0; np < 2; ++np) {
                LDSM4(bh[np], sbh + np * 16 * ROWB + k16 * 32 + partB);
                LDSM4(bl[np], sbl + np * 16 * ROWB + k16 * 32 + partB);
            }
#pragma unroll
            for (int mi = 0; mi < 4; ++mi)
                LDSM4(af[mi], sah + mi * 16 * ROWB + k16 * 32 + partA);
#pragma unroll
            for (int mi = 0; mi < 4; ++mi)
#pragma unroll
                for (int ni = 0; ni < 4; ++ni) {
                    MMA16816(acc[mi][ni], af[mi], bh[ni >> 1][(ni & 1) * 2],
                             bh[ni >> 1][(ni & 1) * 2 + 1]);
                    MMA16816(acc[mi][ni], af[mi], bl[ni >> 1][(ni & 1) * 2],
                             bl[ni >> 1][(ni & 1) * 2 + 1]);
                }
#pragma unroll
            for (int mi = 0; mi < 4; ++mi)
                LDSM4(af[mi], sal + mi * 16 * ROWB + k16 * 32 + partA);
#pragma unroll
            for (int mi = 0; mi < 4; ++mi)
#pragma unroll
                for (int ni = 0; ni < 4; ++ni)
                    MMA16816(acc[mi][ni], af[mi], bh[ni >> 1][(ni & 1) * 2],
                             bh[ni >> 1][(ni & 1) * 2 + 1]);
        }
        __syncthreads();
        st ^= 1;
    }

    float* outS = (float*)sm;
    const int gid = lane >> 2, tq = lane & 3;
#pragma unroll
    for (int mi = 0; mi < 4; ++mi)
#pragma unroll
        for (int ni = 0; ni < 4; ++ni) {
            int jrow = m0 + 16 * mi + gid;
            int tcol = n0 + 8 * ni + tq * 2;
            float b0 = biasS[jrow], b8 = biasS[jrow + 8];
            outS[jrow * 132 + tcol]           = expf(acc[mi][ni][0] + b0);
            outS[jrow * 132 + tcol + 1]       = expf(acc[mi][ni][1] + b0);
            outS[(jrow + 8) * 132 + tcol]     = expf(acc[mi][ni][2] + b8);
            outS[(jrow + 8) * 132 + tcol + 1] = expf(acc[mi][ni][3] + b8);
        }
    __syncthreads();

    for (int i = tid; i < 128 * 32; i += 256) {
        int r = i >> 5, q = i & 31;
        int d = d0 + r;
        int rr = rt0 + q * 4;
        int b = rr / Tdim, t = rr - b * Tdim;
        if (d < XDdim)
            *(float4*)&y_out[((size_t)b * XDdim + d) * Tdim + t] =
                *(float4*)&outS[r * 132 + q * 4];
    }
}

// ============== K1h2: h2 = tanh(Wzx2 @ h1 + bzx2), 3 terms (unchanged) ========
__global__ __launch_bounds__(256, 2) void h2gemm_kernel(const float* __restrict__ bzx2) {
    extern __shared__ char sm[];
    const uint32_t smb = smem_u32(sm);
    const int tid = threadIdx.x, lane = tid & 31, w = tid >> 5;
    const int rt0 = blockIdx.y * 128;

    float* biasS = (float*)(sm + 81920);
    if (tid < 128) biasS[tid] = bzx2[tid];

    const int rowE = tid >> 2, rowO = 64 + (tid >> 2);
    const int rrE = rt0 + rowE, rrO = rt0 + rowO;
    const int bE = rrE / Tdim, tE = rrE - bE * Tdim;
    const int bO = rrO / Tdim, tO = rrO - bO * Tdim;
    const size_t boffE = ((size_t)bE * TPAD + tE) * Hdim;
    const size_t boffO = ((size_t)bO * TPAD + tO) * Hdim;

    auto load_stage = [&](int st, int dk) {
        uint32_t base = smb + st * STG2;
#pragma unroll
        for (int i = 0; i < 8; ++i) {
            int rem = (i & 1) * 256 + tid;
            int row = rem >> 2, seg = rem & 3;
            const __nv_bfloat16* src;
            if (i < 4) {
                const __nv_bfloat16* M = (i < 2) ? d_zx2h : d_zx2l;
                src = M + (size_t)row * Hdim + dk * 32 + seg * 8;
            } else {
                const __nv_bfloat16* M = (i < 6) ? d_h1h : d_h1l;
                src = M + ((i & 1) ? boffO : boffE) + dk * 32 + seg * 8;
            }
            cpa16(base + (i >> 1) * 10240 + row * ROWB + seg * 16, src, 16);
        }
        CP_COMMIT();
    };

    float acc[4][4][4];
#pragma unroll
    for (int mi = 0; mi < 4; ++mi)
#pragma unroll
        for (int ni = 0; ni < 4; ++ni)
#pragma unroll
            for (int q = 0; q < 4; ++q) acc[mi][ni][q] = 0.f;

    const int m0 = (w >> 2) * 64, n0 = (w & 3) * 32;
    const uint32_t partA = ((lane & 7) + ((lane >> 3) & 1) * 8) * ROWB + ((lane >> 4) & 1) * 16;
    const uint32_t partB = (((lane >> 4) & 1) * 8 + (lane & 7)) * ROWB + ((lane >> 3) & 1) * 16;

    load_stage(0, 0);
    int st = 0;

    for (int c = 0; c < 4; ++c) {
        if (c < 3) { load_stage(st ^ 1, c + 1); CP_WAIT1(); }
        else       { CP_WAIT0(); }
        __syncthreads();

        uint32_t sah = smb + st * STG2 + m0 * ROWB;
        uint32_t sal = sah + 10240;
        uint32_t sbh = smb + st * STG2 + 20480 + n0 * ROWB;
        uint32_t sbl = sbh + 10240;
#pragma unroll
        for (int k16 = 0; k16 < 2; ++k16) {
            uint32_t bh[2][4], bl[2][4], af[4][4];
#pragma unroll
            for (int np = 0; np < 2; ++np) {
                LDSM4(bh[np], sbh + np * 16 * ROWB + k16 * 32 + partB);
                LDSM4(bl[np], sbl + np * 16 * ROWB + k16 * 32 + partB);
            }
#pragma unroll
            for (int mi = 0; mi < 4; ++mi)
                LDSM4(af[mi], sah + mi * 16 * ROWB + k16 * 32 + partA);
#pragma unroll
            for (int mi = 0; mi < 4; ++mi)
#pragma unroll
                for (int ni = 0; ni < 4; ++ni) {
                    MMA16816(acc[mi][ni], af[mi], bh[ni >> 1][(ni & 1) * 2],
                             bh[ni >> 1][(ni & 1) * 2 + 1]);
                    MMA16816(acc[mi][ni], af[mi], bl[ni >> 1][(ni & 1) * 2],
                             bl[ni >> 1][(ni & 1) * 2 + 1]);
                }
#pragma unroll
            for (int mi = 0; mi < 4; ++mi)
                LDSM4(af[mi], sal + mi * 16 * ROWB + k16 * 32 + partA);
#pragma unroll
            for (int mi = 0; mi < 4; ++mi)
#pragma unroll
                for (int ni = 0; ni < 4; ++ni)
                    MMA16816(acc[mi][ni], af[mi], bh[ni >> 1][(ni & 1) * 2],
                             bh[ni >> 1][(ni & 1) * 2 + 1]);
        }
        __syncthreads();
        st ^= 1;
    }

    float* outS = (float*)sm;
    const int gid = lane >> 2, tq = lane & 3;
#pragma unroll
    for (int mi = 0; mi < 4; ++mi)
#pragma unroll
        for (int ni = 0; ni < 4; ++ni) {
            int jrow = m0 + 16 * mi + gid;
            int tcol = n0 + 8 * ni + tq * 2;
            float b0 = biasS[jrow], b8 = biasS[jrow + 8];
            outS[tcol * 132 + jrow]           = tanhfast(acc[mi][ni][0] + b0);
            outS[(tcol + 1) * 132 + jrow]     = tanhfast(acc[mi][ni][1] + b0);
            outS[tcol * 132 + jrow + 8]       = tanhfast(acc[mi][ni][2] + b8);
            outS[(tcol + 1) * 132 + jrow + 8] = tanhfast(acc[mi][ni][3] + b8);
        }
    __syncthreads();

    for (int i = tid; i < 128 * 32; i += 256) {
        int r = i >> 5, q = i & 31;
        int rr = rt0 + r;
        int b = rr / Tdim, t = rr - b * Tdim;
        float4 v = *(float4*)&outS[r * 132 + q * 4];
        __nv_bfloat162 h01, h23, l01, l23;
        h01.x = __float2bfloat16(v.x); h01.y = __float2bfloat16(v.y);
        h23.x = __float2bfloat16(v.z); h23.y = __float2bfloat16(v.w);
        l01.x = __float2bfloat16(v.x - __bfloat162float(h01.x));
        l01.y = __float2bfloat16(v.y - __bfloat162float(h01.y));
        l23.x = __float2bfloat16(v.z - __bfloat162float(h23.x));
        l23.y = __float2bfloat16(v.w - __bfloat162float(h23.y));
        size_t base = ((size_t)b * TPAD + t) * Hdim + q * 4;
        *(__nv_bfloat162*)&d_h2h[base]     = h01;
        *(__nv_bfloat162*)&d_h2h[base + 2] = h23;
        *(__nv_bfloat162*)&d_h2l[base]     = l01;
        *(__nv_bfloat162*)&d_h2l[base + 2] = l23;
    }
}

// ============== K2: LSTM (reverted to R15 design: 64 blocks, MUFU.TANH) =======
#define LSTM_SMEM3 (139264 + 2 * 4352)
#define WROW 272
__global__ __launch_bounds__(512, 1) void lstm_mma_kernel(const float* __restrict__ Whh) {
    extern __shared__ char sm[];
    __nv_bfloat16* Wsm = (__nv_bfloat16*)sm;
    __nv_bfloat16* hAbuf[2] = {(__nv_bfloat16*)(sm + 139264),
                               (__nv_bfloat16*)(sm + 139264 + 4352)};

    const int tid = threadIdx.x, lane = tid & 31, w = tid >> 5;
    const int b0 = blockIdx.x * 4;
    const int gb0 = w * 32;

    for (int idx = tid; idx < G4 * Hdim; idx += 512) {
        int g = idx >> 7, k = idx & 127;
        int q = g >> 7;
        int j = g & 127;
        int pr = (j >> 3) * 32 + q * 8 + (j & 7);
        Wsm[pr * 136 + k] = __float2bfloat16(Whh[idx]);
    }
    for (int idx = tid; idx < 2 * 16 * 136; idx += 512)
        ((__nv_bfloat16*)(sm + 139264))[idx] = __float2bfloat16(0.f);
    __syncthreads();

    uint32_t bw[8][8];
    const uint32_t partB = (((lane >> 4) & 1) * 8 + (lane & 7)) * WROW + ((lane >> 3) & 1) * 16;
    const uint32_t partA = ((lane & 7) + ((lane >> 3) & 1) * 8) * WROW + ((lane >> 4) & 1) * 16;
    {
        uint32_t wbase = smem_u32(Wsm) + gb0 * WROW;
#pragma unroll
        for (int kk = 0; kk < 8; ++kk) {
            LDSM4(&bw[kk][0], wbase + kk * 32 + partB);
            LDSM4(&bw[kk][4], wbase + 16 * WROW + kk * 32 + partB);
        }
    }

    const int prow = lane >> 2, pcol = (lane & 3) * 2;
    const bool pvalid = (prow < 4);
    const int hbase = w * 8 + pcol;

    float2 pf[4];
#pragma unroll
    for (int ni = 0; ni < 4; ++ni)
        pf[ni] = pvalid
            ? *(const float2*)&d_P[((size_t)(Tdim - 1) * Bdim + b0 + prow) * G4 +
                                   ni * 128 + hbase]
            : make_float2(0.f, 0.f);

    float cc0 = 0.f, cc1 = 0.f;
    int cur = 0;

    for (int t = Tdim - 1; t >= 0; --t) {
        float acc[4][4];
#pragma unroll
        for (int ni = 0; ni < 4; ++ni) {
            acc[ni][0] = pf[ni].x; acc[ni][1] = pf[ni].y;
            acc[ni][2] = 0.f; acc[ni][3] = 0.f;
        }
        if (t > 0 && pvalid) {
#pragma unroll
            for (int ni = 0; ni < 4; ++ni)
                pf[ni] = *(const float2*)&d_P[((size_t)(t - 1) * Bdim + b0 + prow) * G4 +
                                              ni * 128 + hbase];
        }

        const uint32_t habase = smem_u32(hAbuf[cur]);
#pragma unroll
        for (int kk = 0; kk < 8; ++kk) {
            uint32_t af[4];
            LDSM4(af, habase + kk * 32 + partA);
#pragma unroll
            for (int ni = 0; ni < 4; ++ni)
                MMA16816(acc[ni], af, bw[kk][(ni >> 1) * 4 + (ni & 1) * 2],
                         bw[kk][(ni >> 1) * 4 + (ni & 1) * 2 + 1]);
        }

        if (pvalid) {
            cc0 = sig_hw(acc[1][0]) * cc0 + sig_hw(acc[0][0]) * tanh_hw(acc[2][0]);
            float h0 = sig_hw(acc[3][0]) * tanh_hw(cc0);
            cc1 = sig_hw(acc[1][1]) * cc1 + sig_hw(acc[0][1]) * tanh_hw(acc[2][1]);
            float h1 = sig_hw(acc[3][1]) * tanh_hw(cc1);
            __nv_bfloat162 hh;
            hh.x = __float2bfloat16(h0); hh.y = __float2bfloat16(h1);
            *(__nv_bfloat162*)&hAbuf[cur ^ 1][prow * 136 + hbase] = hh;
            *(float2*)&d_G[((size_t)t * Bdim + b0 + prow) * Hdim + hbase] =
                make_float2(h0, h1);
        }
        __syncthreads();
        cur ^= 1;
    }
}

// ============== K3: inference scan (unchanged) ==============
__global__ __launch_bounds__(128) void infer_kernel(
    const float* __restrict__ eps,
    const float* __restrict__ Wzz, const float* __restrict__ bzz,
    const float* __restrict__ Wim, const float* __restrict__ bim,
    const float* __restrict__ Wil, const float* __restrict__ bil,
    float* __restrict__ zm_out, float* __restrict__ zl_out) {
    __shared__ float Wzzs[16 * 128];
    __shared__ float Wims[128 * 16];
    __shared__ float Wils[128 * 16];
    __shared__ float zsm[16];
    __shared__ float gts[128];
    __shared__ float pm_s[8][16], pl_s[8][16];

    const int tid = threadIdx.x;
    const int b = blockIdx.x;

    for (int idx = tid; idx < 2048; idx += 128) {
        { int j = idx >> 4, k = idx & 15; Wzzs[k * 128 + j] = Wzz[idx]; }
        { int m = idx >> 7, j = idx & 127;
          Wims[j * 16 + m] = Wim[idx]; Wils[j * 16 + m] = Wil[idx]; }
    }
    if (tid < 16) zsm[tid] = 0.f;
    float bzzr = bzz[tid];
    float bimr = 0.f, bilr = 0.f;
    if (tid < 16) { bimr = bim[tid]; bilr = bil[tid]; }
    __syncthreads();

    const int m = tid & 15, part = tid >> 4;
    for (int t = 0; t < Tdim; ++t) {
        {
            float s = bzzr;
#pragma unroll
            for (int k = 0; k < 16; ++k) s += zsm[k] * Wzzs[k * 128 + tid];
            float g = d_G[(size_t)t * Bdim * Hdim + (size_t)b * Hdim + tid];
            gts[tid] = 0.5f * (tanhf(s) + g);
        }
        __syncthreads();
        {
            float sm2 = 0.f, sl2 = 0.f;
            int jb = part * 16;
#pragma unroll
            for (int k = 0; k < 16; ++k) {
                float g = gts[jb + k];
                sm2 += g * Wims[(jb + k) * 16 + m];
                sl2 += g * Wils[(jb + k) * 16 + m];
            }
            pm_s[part][m] = sm2; pl_s[part][m] = sl2;
        }
        __syncthreads();
        if (tid < 16) {
            float mean = bimr, lv = bilr;
#pragma unroll
            for (int p = 0; p < 8; ++p) { mean += pm_s[p][tid]; lv += pl_s[p][tid]; }
            int o = t * Bdim * ZDdim + b * ZDdim + tid;
            float e = eps[o];
            float z = mean + e * expf(0.5f * lv);
            zsm[tid] = z;
            zm_out[o] = mean; zl_out[o] = lv; d_Z[o] = z;
        }
        __syncthreads();
    }
}

// ============== K4: generation small part (stops at h1, unchanged) ==============
#define GEN_SMEM ((512 + 2048 + 1536 + 2048) * 4)
__global__ __launch_bounds__(256) void gen_kernel(
    const float* __restrict__ Wg1, const float* __restrict__ bg1,
    const float* __restrict__ Wg2, const float* __restrict__ bg2,
    const float* __restrict__ Wp1, const float* __restrict__ bp1,
    const float* __restrict__ Wp2, const float* __restrict__ bp2,
    const float* __restrict__ Wpm, const float* __restrict__ bpm,
    const float* __restrict__ Wpl, const float* __restrict__ bpl,
    const float* __restrict__ Wzx1, const float* __restrict__ bzx1,
    float* __restrict__ zmp_out, float* __restrict__ zlp_out,
    float* __restrict__ zo_out) {
    extern __shared__ char sm[];
    float* smf = (float*)sm;
    float* zrow  = smf;
    float* Wzx1s = zrow + 512;
    float* sw    = Wzx1s + 2048;
    float* a1s   = sw + 1536;
    float* p1s   = a1s + 512;
    float* zps   = p1s + 512;
    float* gts   = zps + 512;

    const int tid = threadIdx.x;
    const int b = blockIdx.y;
    const int t0 = blockIdx.x * 32;
    const int nrows = min(32, Tdim - t0);

    for (int idx = tid; idx < 2048; idx += 256) {
        int j = idx >> 4, k = idx & 15;
        Wzx1s[k * 128 + j] = Wzx1[idx];
    }
    if (tid < 256) {
        sw[tid] = Wg1[tid]; sw[256 + tid] = Wg2[tid]; sw[512 + tid] = Wp1[tid];
        sw[768 + tid] = Wp2[tid]; sw[1024 + tid] = Wpm[tid]; sw[1280 + tid] = Wpl[tid];
    }
    for (int idx = tid; idx < 512; idx += 256) {
        int r = idx >> 4, m = idx & 15;
        zrow[idx] = (r < nrows) ? d_Z[(size_t)(t0 + r) * Bdim * ZDdim + b * ZDdim + m] : 0.f;
    }
    __syncthreads();

    for (int idx = tid; idx < 512; idx += 256) {
        int r = idx & 31, k = idx >> 5;
        if (r < nrows)
            zo_out[(size_t)b * ZDdim * Tdim + (size_t)k * Tdim + t0 + r] = zrow[r * 16 + k];
    }

    for (int idx = tid; idx < 512; idx += 256) {
        int r = idx >> 4, m = idx & 15;
        float s1 = bg1[m], s2 = bp1[m];
#pragma unroll
        for (int k = 0; k < 16; ++k) {
            float z = zrow[r * 16 + k];
            s1 += z * sw[m * 16 + k];
            s2 += z * sw[512 + m * 16 + k];
        }
        a1s[idx] = fmaxf(s1, 0.f);
        p1s[idx] = fmaxf(s2, 0.f);
    }
    __syncthreads();
    for (int idx = tid; idx < 512; idx += 256) {
        int r = idx >> 4, m = idx & 15;
        float s1 = bg2[m], s2 = bp2[m];
#pragma unroll
        for (int k = 0; k < 16; ++k) {
            s1 += a1s[r * 16 + k] * sw[256 + m * 16 + k];
            s2 += p1s[r * 16 + k] * sw[768 + m * 16 + k];
        }
        gts[idx] = sigm(s1);
        zps[idx] = s2;
    }
    __syncthreads();
    for (int idx = tid; idx < 512; idx += 256) {
        int r = idx >> 4, m = idx & 15;
        float pm = bpm[m], pl = bpl[m];
#pragma unroll
        for (int k = 0; k < 16; ++k) {
            float z = zrow[r * 16 + k];
            pm += z * sw[1024 + m * 16 + k];
            pl += fmaxf(zps[r * 16 + k], 0.f) * sw[1280 + m * 16 + k];
        }
        float gate = gts[idx];
        float zmp = (1.f - gate) * pm + gate * zps[idx];
        float sp = (pl > 20.f) ? pl : log1pf(expf(pl));
        float zlp = logf(sp);
        if (r < nrows) {
            int o = (t0 + r) * Bdim * ZDdim + b * ZDdim + m;
            zmp_out[o] = zmp; zlp_out[o] = zlp;
        }
    }

    for (int idx = tid; idx < 4096; idx += 256) {
        int r = idx >> 7, j = idx & 127;
        if (r < nrows) {
            float s = bzx1[j];
#pragma unroll
            for (int k = 0; k < 16; ++k) s += zrow[r * 16 + k] * Wzx1s[k * 128 + j];
            float v = tanhf(s);
            __nv_bfloat16 h = __float2bfloat16(v);
            __nv_bfloat16 l = __float2bfloat16(v - __bfloat162float(h));
            size_t o = ((size_t)b * TPAD + t0 + r) * Hdim + j;
            d_h1h[o] = h; d_h1l[o] = l;
        }
    }
}

// =====================================================================
extern "C" void kernel_launch(void* const* d_in, const int* in_sizes, int n_in,
                              void* d_out, int out_size) {
    const float* x    = (const float*)d_in[0];
    const float* eps  = (const float*)d_in[1];
    const float* Wih  = (const float*)d_in[2];
    const float* Whh  = (const float*)d_in[3];
    const float* bih  = (const float*)d_in[4];
    const float* bhh  = (const float*)d_in[5];
    const float* Wzz  = (const float*)d_in[6];
    const float* bzz  = (const float*)d_in[7];
    const float* Wim  = (const float*)d_in[8];
    const float* bim  = (const float*)d_in[9];
    const float* Wil  = (const float*)d_in[10];
    const float* bil  = (const float*)d_in[11];
    const float* Wg1  = (const float*)d_in[12];
    const float* bg1  = (const float*)d_in[13];
    const float* Wg2  = (const float*)d_in[14];
    const float* bg2  = (const float*)d_in[15];
    const float* Wp1  = (const float*)d_in[16];
    const float* bp1  = (const float*)d_in[17];
    const float* Wp2  = (const float*)d_in[18];
    const float* bp2  = (const float*)d_in[19];
    const float* Wpm  = (const float*)d_in[20];
    const float* bpm  = (const float*)d_in[21];
    const float* Wpl  = (const float*)d_in[22];
    const float* bpl  = (const float*)d_in[23];
    const float* Wzx1 = (const float*)d_in[24];
    const float* bzx1 = (const float*)d_in[25];
    const float* Wzx2 = (const float*)d_in[26];
    const float* bzx2 = (const float*)d_in[27];
    const float* Wgy  = (const float*)d_in[28];
    const float* bgy  = (const float*)d_in[29];

    float* out = (float*)d_out;
    float* y_out   = out;
    float* zm_out  = out + 39398400;
    float* zl_out  = out + 40627200;
    float* zmp_out = out + 41856000;
    float* zlp_out = out + 43084800;
    float* zo_out  = out + 44313600;

    cudaFuncSetAttribute(gemm_mma_kernel, cudaFuncAttributeMaxDynamicSharedMemorySize, MMA_SMEM3);
    cudaFuncSetAttribute(ygemm_kernel, cudaFuncAttributeMaxDynamicSharedMemorySize, MMA_SMEM2);
    cudaFuncSetAttribute(h2gemm_kernel, cudaFuncAttributeMaxDynamicSharedMemorySize, MMA_SMEM2);
    cudaFuncSetAttribute(lstm_mma_kernel, cudaFuncAttributeMaxDynamicSharedMemorySize, LSTM_SMEM3);
    cudaFuncSetAttribute(gen_kernel,  cudaFuncAttributeMaxDynamicSharedMemorySize, GEN_SMEM);

    convert_x_kernel<<<dim3(170, Bdim), 256>>>(x);
    convert_w_kernel<<<(G4 * XDpad + 255) / 256, 256>>>(Wih);
    convert_gy_kernel<<<(640 * Hdim + 255) / 256, 256>>>(Wgy);
    convert_zx2_kernel<<<(Hdim * Hdim + 255) / 256, 256>>>(Wzx2);
    gemm_mma_kernel<<<dim3(4, NROWS / 128), 256, MMA_SMEM3>>>(bih, bhh);
    lstm_mma_kernel<<<64, 512, LSTM_SMEM3>>>(Whh);
    infer_kernel<<<256, 128>>>(eps, Wzz, bzz, Wim, bim, Wil, bil, zm_out, zl_out);
    gen_kernel<<<dim3(10, Bdim), 256, GEN_SMEM>>>(
        Wg1, bg1, Wg2, bg2, Wp1, bp1, Wp2, bp2, Wpm, bpm, Wpl, bpl,
        Wzx1, bzx1, zmp_out, zlp_out, zo_out);
    h2gemm_kernel<<<dim3(1, NROWS / 128), 256, MMA_SMEM2>>>(bzx2);
    ygemm_kernel<<<dim3(5, NROWS / 128), 256, MMA_SMEM2>>>(bgy, y_out);
}